// round 16
// baseline (speedup 1.0000x reference)
#include <cuda_runtime.h>

// PS-ROI Pooling via channel transpose + coalesced pooling.
// features [4,1029,64,64] f32, rois [1024,5] f32, out [1024,21,7,7] f32.
//
// NUMERICS CONTRACT (frozen, validated R10-R15: rel_err 9.5e-7):
//  - bounds: separate __fmul_rn/__fadd_rn, rintf, __fdividef (div.full.f32,
//    XLA:GPU's fast f32 division) for bin = roi/7 and final s/area.
//  - window sums exact f32 (order-insensitive at this tolerance).
//
// PERF (R16): previous kernels were L1tex-wavefront bound: each warp load
// touched up to 32 distinct lines (lane = distinct plane). Two-pass fix:
//  Pass 1: transpose f[b, d*49+g, cell] -> t[(b*49+g), cell, d] via smem
//          tiles; both global sides coalesced (~1M wavefronts, BW-bound).
//  Pass 2: warp per (roi, g); lanes 0..20 = d read 21 CONTIGUOUS floats
//          per window cell (1-2 wavefronts/cell, identical window per lane).

#define BATCH 4
#define POOLED 7
#define OUTPUT_DIM 21
#define CHANNELS (OUTPUT_DIM * POOLED * POOLED)  // 1029
#define H 64
#define W 64
#define SPATIAL_SCALE 0.0625f
#define NUM_ROIS 1024
#define PER_ROI CHANNELS                         // 1029
#define PLANE (H * W)                            // 4096
#define NBINS 49
#define NBG (BATCH * NBINS)                      // 196

// t[(b*49+g)][cell][d], d = 0..20 contiguous.  196*4096*21*4B = 67.7 MB
__device__ float g_t[(size_t)NBG * PLANE * OUTPUT_DIM];

// ---------------- Pass 1: transpose ----------------
// grid (196, 16), block 256. Block (bg, chunk) moves 256 cells x 21 d.
__global__ __launch_bounds__(256)
void psroi_transpose_kernel(const float* __restrict__ f)
{
    __shared__ float tile[OUTPUT_DIM][257];   // pad -> conflict-free

    const int bg    = blockIdx.x;
    const int b     = bg / NBINS;
    const int g     = bg % NBINS;
    const int cell0 = blockIdx.y * 256;
    const int tid   = threadIdx.x;

    // Read: 21 coalesced row segments (one per d).
#pragma unroll
    for (int d = 0; d < OUTPUT_DIM; ++d) {
        int c = d * NBINS + g;
        tile[d][tid] = f[((size_t)(b * CHANNELS + c)) * PLANE + cell0 + tid];
    }
    __syncthreads();

    // Write: 21*256 = 5376 elements, address = tbase + e -> fully coalesced.
    const size_t tbase = ((size_t)bg * PLANE + cell0) * OUTPUT_DIM;
#pragma unroll
    for (int it = 0; it < OUTPUT_DIM; ++it) {
        int e  = it * 256 + tid;
        int cl = e / OUTPUT_DIM;
        int dd = e % OUTPUT_DIM;
        g_t[tbase + e] = tile[dd][cl];
    }
}

// ---------------- Pass 2: pooling ----------------
// grid 1024 (one block per ROI), block 256 = 8 warps; warp handles bins
// g = warpid + 8k; lanes 0..20 = d.
__global__ __launch_bounds__(256)
void psroi_pool_kernel(const float* __restrict__ rois,
                       float* __restrict__ out)
{
    __shared__ int   sh_hs[POOLED], sh_he[POOLED];
    __shared__ int   sh_ws[POOLED], sh_we[POOLED];
    __shared__ float sh_ah[POOLED], sh_aw[POOLED];
    __shared__ float sh_out[PER_ROI];
    __shared__ int   sh_b;

    const int n   = blockIdx.x;
    const int tid = threadIdx.x;

    if (tid < 2 * POOLED) {
        const float* r = rois + n * 5;
        const int axis = tid / POOLED;   // 0 -> h (y: r[2],r[4]), 1 -> w (x: r[1],r[3])
        const int p    = tid % POOLED;

        float c_start = axis ? r[1] : r[2];
        float c_end   = axis ? r[3] : r[4];

        float rs = __fmul_rn(rintf(c_start), SPATIAL_SCALE);
        float re = __fmul_rn(rintf(__fadd_rn(c_end, 1.0f)), SPATIAL_SCALE);
        float roi_sz = fmaxf(__fsub_rn(re, rs), 0.1f);
        float bin    = __fdividef(roi_sz, (float)POOLED);   // div.full.f32 (XLA match)

        float fp = (float)p;
        float v0 = __fadd_rn(__fmul_rn(fp, bin), rs);
        float v1 = __fadd_rn(__fmul_rn(__fadd_rn(fp, 1.0f), bin), rs);

        int s = (int)fminf(fmaxf(floorf(v0), 0.0f), 64.0f);
        int e = (int)fminf(fmaxf(ceilf (v1), 0.0f), 64.0f);

        if (axis == 0) {
            sh_hs[p] = s; sh_he[p] = e;
            sh_ah[p] = (float)(e - s);
        } else {
            sh_ws[p] = s; sh_we[p] = e;
            sh_aw[p] = (float)(e - s);
        }
        if (tid == 0) sh_b = (int)rois[n * 5];
    }
    __syncthreads();

    const int warpid = tid >> 5;
    const int lane   = tid & 31;
    const int b      = sh_b;

    for (int g = warpid; g < NBINS; g += 8) {
        const int ph = g / POOLED, pw = g % POOLED;
        const int hs = sh_hs[ph], he = sh_he[ph];
        const int ws = sh_ws[pw], we = sh_we[pw];
        const int nw = we - ws;

        if (lane < OUTPUT_DIM) {
            float acc = 0.0f;
            const float* tb = g_t
                + ((size_t)(b * NBINS + g) * PLANE) * OUTPUT_DIM + lane;
            for (int h = hs; h < he; ++h) {
                const float* rowp = tb + (h * W + ws) * OUTPUT_DIM;
#pragma unroll 2
                for (int j = 0; j < nw; ++j)
                    acc += __ldg(rowp + j * OUTPUT_DIM);
            }
            float area = sh_ah[ph] * sh_aw[pw];
            sh_out[lane * NBINS + g] = (area > 0.0f) ? __fdividef(acc, area)
                                                     : 0.0f;
        }
    }
    __syncthreads();

    // Coalesced output write.
    float* out_roi = out + (size_t)n * PER_ROI;
    for (int i = tid; i < PER_ROI; i += 256)
        out_roi[i] = sh_out[i];
}

extern "C" void kernel_launch(void* const* d_in, const int* in_sizes, int n_in,
                              void* d_out, int out_size)
{
    const float* features = (const float*)d_in[0];
    const float* rois     = (const float*)d_in[1];
    float* out            = (float*)d_out;

    dim3 tgrid(NBG, PLANE / 256);   // (196, 16)
    psroi_transpose_kernel<<<tgrid, 256>>>(features);
    psroi_pool_kernel<<<NUM_ROIS, 256>>>(rois, out);
}

// round 17
// speedup vs baseline: 1.1590x; 1.1590x over previous
#include <cuda_runtime.h>

// PS-ROI Pooling via channel transpose + thread-per-output coalesced pooling.
// features [4,1029,64,64] f32, rois [1024,5] f32, out [1024,21,7,7] f32.
//
// NUMERICS CONTRACT (frozen, validated R10-R16: rel_err 9.5e-7):
//  - bounds: separate __fmul_rn/__fadd_rn, rintf, __fdividef (div.full.f32,
//    XLA:GPU's fast f32 division) for bin = roi/7 and final s/area.
//  - window sums exact f32 (order-insensitive at this tolerance).
//
// PERF (R17): v16 proved transpose ~18us but its pass-2 was warp-serial
// (42us, all pipes <11%). New pass 2: thread per output, j = g*21+d
// ordering -> warp lanes sweep d fastest; for fixed (g,cell) 21 lanes read
// 21 CONSECUTIVE floats (~2 lines vs 32 scattered planes). ~1.3M wavefronts
// total (vs ~4M direct), 262K threads of TLP, h-unroll-2 for MLP, smem-
// staged coalesced output.

#define BATCH 4
#define POOLED 7
#define OUTPUT_DIM 21
#define CHANNELS (OUTPUT_DIM * POOLED * POOLED)  // 1029
#define H 64
#define W 64
#define SPATIAL_SCALE 0.0625f
#define NUM_ROIS 1024
#define PER_ROI CHANNELS                         // 1029
#define PLANE (H * W)                            // 4096
#define NBINS 49
#define NBG (BATCH * NBINS)                      // 196
#define ROWSTRIDE (W * OUTPUT_DIM)               // 1344 floats per image row

// t[(b*49+g)][cell][d], d contiguous.  196*4096*21*4B = 67.6 MB
__device__ float g_t[(size_t)NBG * PLANE * OUTPUT_DIM];

// ---------------- Pass 1: transpose ----------------
// grid (196, 16), block 256. Block (bg, chunk) moves 256 cells x 21 d.
__global__ __launch_bounds__(256)
void psroi_transpose_kernel(const float* __restrict__ f)
{
    __shared__ float tile[OUTPUT_DIM][257];   // pad -> conflict-free

    const int bg    = blockIdx.x;
    const int b     = bg / NBINS;
    const int g     = bg % NBINS;
    const int cell0 = blockIdx.y * 256;
    const int tid   = threadIdx.x;

    // Read: 21 coalesced row segments (one per d).
#pragma unroll
    for (int d = 0; d < OUTPUT_DIM; ++d) {
        int c = d * NBINS + g;
        tile[d][tid] = f[((size_t)(b * CHANNELS + c)) * PLANE + cell0 + tid];
    }
    __syncthreads();

    // Write: 5376 floats = 1344 float4, contiguous -> coalesced STG.128.
    const size_t tbase = ((size_t)bg * PLANE + cell0) * OUTPUT_DIM;
    float4* dst4 = (float4*)(g_t + tbase);
#pragma unroll
    for (int q = 0; q < 1344 / 256; ++q) {          // 5 full passes
        int e4 = q * 256 + tid;
        int e  = e4 * 4;
        float4 v;
        v.x = tile[(e + 0) % OUTPUT_DIM][(e + 0) / OUTPUT_DIM];
        v.y = tile[(e + 1) % OUTPUT_DIM][(e + 1) / OUTPUT_DIM];
        v.z = tile[(e + 2) % OUTPUT_DIM][(e + 2) / OUTPUT_DIM];
        v.w = tile[(e + 3) % OUTPUT_DIM][(e + 3) / OUTPUT_DIM];
        dst4[e4] = v;
    }
    {   // tail: 1344 = 5*256 + 64
        int e4 = 5 * 256 + tid;
        if (tid < 64) {
            int e = e4 * 4;
            float4 v;
            v.x = tile[(e + 0) % OUTPUT_DIM][(e + 0) / OUTPUT_DIM];
            v.y = tile[(e + 1) % OUTPUT_DIM][(e + 1) / OUTPUT_DIM];
            v.z = tile[(e + 2) % OUTPUT_DIM][(e + 2) / OUTPUT_DIM];
            v.w = tile[(e + 3) % OUTPUT_DIM][(e + 3) / OUTPUT_DIM];
            dst4[e4] = v;
        }
    }
}

// ---------------- Pass 2: pooling, thread per output ----------------
// grid 1024 (block per ROI), 256 threads; j = g*21 + d (d fastest in warp).
__global__ __launch_bounds__(256)
void psroi_pool_kernel(const float* __restrict__ rois,
                       float* __restrict__ out)
{
    __shared__ int   sh_hs[POOLED], sh_he[POOLED];
    __shared__ int   sh_ws[POOLED], sh_we[POOLED];
    __shared__ float sh_ah[POOLED], sh_aw[POOLED];
    __shared__ float sh_out[PER_ROI];
    __shared__ int   sh_b;

    const int n   = blockIdx.x;
    const int tid = threadIdx.x;

    if (tid < 2 * POOLED) {
        const float* r = rois + n * 5;
        const int axis = tid / POOLED;   // 0 -> h (y: r[2],r[4]), 1 -> w (x: r[1],r[3])
        const int p    = tid % POOLED;

        float c_start = axis ? r[1] : r[2];
        float c_end   = axis ? r[3] : r[4];

        float rs = __fmul_rn(rintf(c_start), SPATIAL_SCALE);
        float re = __fmul_rn(rintf(__fadd_rn(c_end, 1.0f)), SPATIAL_SCALE);
        float roi_sz = fmaxf(__fsub_rn(re, rs), 0.1f);
        float bin    = __fdividef(roi_sz, (float)POOLED);   // div.full.f32 (XLA match)

        float fp = (float)p;
        float v0 = __fadd_rn(__fmul_rn(fp, bin), rs);
        float v1 = __fadd_rn(__fmul_rn(__fadd_rn(fp, 1.0f), bin), rs);

        int s = (int)fminf(fmaxf(floorf(v0), 0.0f), 64.0f);
        int e = (int)fminf(fmaxf(ceilf (v1), 0.0f), 64.0f);

        if (axis == 0) {
            sh_hs[p] = s; sh_he[p] = e;
            sh_ah[p] = (float)(e - s);
        } else {
            sh_ws[p] = s; sh_we[p] = e;
            sh_aw[p] = (float)(e - s);
        }
        if (tid == 0) sh_b = (int)rois[n * 5];
    }
    __syncthreads();

    const int b = sh_b;

    for (int j = tid; j < PER_ROI; j += 256) {
        const int g = j / OUTPUT_DIM;          // bin (ph*7+pw)
        const int d = j - g * OUTPUT_DIM;      // lane-fast dim
        const int ph = g / POOLED, pw = g % POOLED;

        const int hs = sh_hs[ph], he = sh_he[ph];
        const int ws = sh_ws[pw];
        const int nw = sh_we[pw] - ws;

        const float* tb = g_t
            + ((size_t)(b * NBINS + g) * PLANE + ws) * OUTPUT_DIM + d;

        float a0 = 0.0f, a1 = 0.0f;
        int h = hs;
        for (; h + 2 <= he; h += 2) {
            const float* r0 = tb + h * ROWSTRIDE;
            const float* r1 = r0 + ROWSTRIDE;
#pragma unroll 3
            for (int w = 0; w < nw; ++w) {
                a0 += __ldg(r0 + w * OUTPUT_DIM);
                a1 += __ldg(r1 + w * OUTPUT_DIM);
            }
        }
        if (h < he) {
            const float* r0 = tb + h * ROWSTRIDE;
#pragma unroll 3
            for (int w = 0; w < nw; ++w)
                a0 += __ldg(r0 + w * OUTPUT_DIM);
        }
        float s = a0 + a1;

        float area = sh_ah[ph] * sh_aw[pw];
        sh_out[d * NBINS + g] = (area > 0.0f) ? __fdividef(s, area) : 0.0f;
    }
    __syncthreads();

    // Coalesced output write.
    float* out_roi = out + (size_t)n * PER_ROI;
    for (int i = tid; i < PER_ROI; i += 256)
        out_roi[i] = sh_out[i];
}

extern "C" void kernel_launch(void* const* d_in, const int* in_sizes, int n_in,
                              void* d_out, int out_size)
{
    const float* features = (const float*)d_in[0];
    const float* rois     = (const float*)d_in[1];
    float* out            = (float*)d_out;

    dim3 tgrid(NBG, PLANE / 256);   // (196, 16)
    psroi_transpose_kernel<<<tgrid, 256>>>(features);
    psroi_pool_kernel<<<NUM_ROIS, 256>>>(rois, out);
}